// round 2
// baseline (speedup 1.0000x reference)
#include <cuda_runtime.h>
#include <cstdint>

typedef unsigned long long ull;

// ---------------- problem constants ----------------
constexpr int NODES  = 100000;
constexpr int EDGES  = 500000;
constexpr int ETYPES = 3;
constexpr int FEAT   = 256;   // F == H*D
constexpr int HEADS  = 4;
constexpr int CLASSES = 349;
constexpr float NEG_SLOPE = 0.2f;

// ---------------- device scratch (allocation-free) ----------------
__device__ float    g_h[(size_t)NODES * FEAT];      // hidden state between layers
__device__ float    g_feat[(size_t)NODES * FEAT];   // per-etype transformed features
__device__ float    g_agg[(size_t)NODES * FEAT];    // summed aggregation across etypes
__device__ float    g_el[NODES * HEADS];
__device__ float    g_er[NODES * HEADS];
__device__ unsigned g_m[NODES * HEADS];             // encoded-float max
__device__ float    g_denom[NODES * HEADS];
__device__ float    g_att[(size_t)EDGES * HEADS];   // logits -> exp values

// monotone float <-> uint encoding for atomicMax on floats (incl. negatives)
__device__ __forceinline__ unsigned fenc(float f) {
    unsigned u = __float_as_uint(f);
    return (u & 0x80000000u) ? ~u : (u | 0x80000000u);
}
__device__ __forceinline__ float fdec(unsigned u) {
    return __uint_as_float((u & 0x80000000u) ? (u ^ 0x80000000u) : ~u);
}
#define ENC_NEG_INF 0x007fffffu

// vector float4 reduction to global (sm_90+)
__device__ __forceinline__ void red4(float* p, float a, float b, float c, float d) {
    asm volatile("red.global.add.v4.f32 [%0], {%1,%2,%3,%4};"
                 :: "l"(p), "f"(a), "f"(b), "f"(c), "f"(d) : "memory");
}

// packed fp32x2 FMA (SASS FFMA2 — 2x fp32 throughput vs 3-reg FFMA)
__device__ __forceinline__ void fma2(ull& acc, ull a, ull b) {
    asm("fma.rn.f32x2 %0, %1, %2, %0;" : "+l"(acc) : "l"(a), "l"(b));
}
__device__ __forceinline__ ull pack_dup(float v) {
    ull r;
    unsigned u = __float_as_uint(v);
    asm("mov.b64 %0, {%1, %1};" : "=l"(r) : "r"(u));
    return r;
}

// ---------------- GEMM: C[M,Ncols] = A[M,256] @ B[256,Ncols] (+bias) ----------------
// BM=128, BN=128, BK=16, 256 threads, 8x8 per thread, row-paired f32x2 accumulators.
__global__ void __launch_bounds__(256) gemm_f32x2(
    const float* __restrict__ A, const float* __restrict__ B,
    float* __restrict__ C, const float* __restrict__ bias,
    int M, int Ncols)
{
    __shared__ float As[16][128];   // [k][row]
    __shared__ float Bs[16][128];   // [k][col]
    const int K = 256;
    int tid = threadIdx.x;
    int tx = tid & 15;   // col group: cols tx*8 .. tx*8+7
    int ty = tid >> 4;   // row group: rows ty*8 .. ty*8+7
    long bm = (long)blockIdx.x * 128;
    int bn  = blockIdx.y * 128;

    ull acc[4][8];   // acc[i2][j]: rows (2*i2, 2*i2+1), col j
#pragma unroll
    for (int i = 0; i < 4; i++)
#pragma unroll
        for (int j = 0; j < 8; j++) acc[i][j] = 0ull;

    int a_r  = tid >> 1;         // 0..127
    int a_kq = (tid & 1) * 8;    // 0 or 8
    int b_r  = tid >> 4;         // 0..15
    int b_c  = (tid & 15) * 8;   // 0..120
    bool bvec = ((Ncols & 3) == 0);
    bool a_ok = (bm + a_r) < M;

    for (int k0 = 0; k0 < K; k0 += 16) {
        // load A tile (128 rows x 16 k): 2 float4 per thread, store k-major
        {
            float4 v0 = make_float4(0.f, 0.f, 0.f, 0.f);
            float4 v1 = make_float4(0.f, 0.f, 0.f, 0.f);
            if (a_ok) {
                const float* ar = A + (bm + a_r) * K + k0 + a_kq;
                v0 = *reinterpret_cast<const float4*>(ar);
                v1 = *reinterpret_cast<const float4*>(ar + 4);
            }
            As[a_kq + 0][a_r] = v0.x;
            As[a_kq + 1][a_r] = v0.y;
            As[a_kq + 2][a_r] = v0.z;
            As[a_kq + 3][a_r] = v0.w;
            As[a_kq + 4][a_r] = v1.x;
            As[a_kq + 5][a_r] = v1.y;
            As[a_kq + 6][a_r] = v1.z;
            As[a_kq + 7][a_r] = v1.w;
        }
        // load B tile (16 k x 128 cols): 2 float4 per thread
        {
            const float* brow = B + (long)(k0 + b_r) * Ncols;
            int col = bn + b_c;
            if (bvec && (col + 7) < Ncols) {
                *reinterpret_cast<float4*>(&Bs[b_r][b_c])     = *reinterpret_cast<const float4*>(brow + col);
                *reinterpret_cast<float4*>(&Bs[b_r][b_c + 4]) = *reinterpret_cast<const float4*>(brow + col + 4);
            } else {
#pragma unroll
                for (int j = 0; j < 8; j++)
                    Bs[b_r][b_c + j] = ((col + j) < Ncols) ? brow[col + j] : 0.f;
            }
        }
        __syncthreads();
#pragma unroll
        for (int k = 0; k < 16; k++) {
            const ull* ap = reinterpret_cast<const ull*>(&As[k][ty * 8]);
            ull a0 = ap[0], a1 = ap[1], a2 = ap[2], a3 = ap[3];
            float4 bv0 = *reinterpret_cast<const float4*>(&Bs[k][tx * 8]);
            float4 bv1 = *reinterpret_cast<const float4*>(&Bs[k][tx * 8 + 4]);
            ull bd[8];
            bd[0] = pack_dup(bv0.x); bd[1] = pack_dup(bv0.y);
            bd[2] = pack_dup(bv0.z); bd[3] = pack_dup(bv0.w);
            bd[4] = pack_dup(bv1.x); bd[5] = pack_dup(bv1.y);
            bd[6] = pack_dup(bv1.z); bd[7] = pack_dup(bv1.w);
#pragma unroll
            for (int j = 0; j < 8; j++) {
                fma2(acc[0][j], a0, bd[j]);
                fma2(acc[1][j], a1, bd[j]);
                fma2(acc[2][j], a2, bd[j]);
                fma2(acc[3][j], a3, bd[j]);
            }
        }
        __syncthreads();
    }

#pragma unroll
    for (int i2 = 0; i2 < 4; i2++) {
        long r0 = bm + ty * 8 + 2 * i2;
#pragma unroll
        for (int j = 0; j < 8; j++) {
            int col = bn + tx * 8 + j;
            if (col >= Ncols) continue;
            float lo = __uint_as_float((unsigned)(acc[i2][j] & 0xffffffffull));
            float hi = __uint_as_float((unsigned)(acc[i2][j] >> 32));
            float b = bias ? bias[col] : 0.f;
            if (r0 < M)     C[r0 * Ncols + col]       = lo + b;
            if (r0 + 1 < M) C[(r0 + 1) * Ncols + col] = hi + b;
        }
    }
}

// ---------------- per-node attention dots + reset m/denom ----------------
__global__ void __launch_bounds__(256) node_att(
    const float* __restrict__ feat,
    const float* __restrict__ al, const float* __restrict__ ar,
    float* __restrict__ el, float* __restrict__ er,
    unsigned* __restrict__ m, float* __restrict__ denom)
{
    int warp = (blockIdx.x * blockDim.x + threadIdx.x) >> 5;
    int lane = threadIdx.x & 31;
    if (warp >= NODES) return;
    const float4* frow = reinterpret_cast<const float4*>(feat + (long)warp * FEAT);
    const float4* alv  = reinterpret_cast<const float4*>(al);
    const float4* arv  = reinterpret_cast<const float4*>(ar);
    float sl = 0.f, sr = 0.f;
#pragma unroll
    for (int q = 0; q < 2; q++) {
        int idx = lane * 2 + q;
        float4 f = frow[idx], a = alv[idx], b = arv[idx];
        sl += f.x * a.x + f.y * a.y + f.z * a.z + f.w * a.w;
        sr += f.x * b.x + f.y * b.y + f.z * b.z + f.w * b.w;
    }
#pragma unroll
    for (int off = 4; off >= 1; off >>= 1) {
        sl += __shfl_xor_sync(0xffffffffu, sl, off);
        sr += __shfl_xor_sync(0xffffffffu, sr, off);
    }
    if ((lane & 7) == 0) {
        int h = lane >> 3;
        el[warp * HEADS + h] = sl;
        er[warp * HEADS + h] = sr;
    }
    if (lane < HEADS) {
        m[warp * HEADS + lane] = ENC_NEG_INF;
        denom[warp * HEADS + lane] = 0.f;
    }
}

// ---------------- edge pass 1: logits + segment max ----------------
__global__ void __launch_bounds__(256) edge_max(
    const int* __restrict__ src, const int* __restrict__ dst,
    const float* __restrict__ el, const float* __restrict__ er,
    float* __restrict__ att, unsigned* __restrict__ m)
{
    int e = blockIdx.x * blockDim.x + threadIdx.x;
    if (e >= EDGES) return;
    int s = src[e], d = dst[e];
    float4 a = *reinterpret_cast<const float4*>(el + (long)s * 4);
    float4 b = *reinterpret_cast<const float4*>(er + (long)d * 4);
    float lg[4] = {a.x + b.x, a.y + b.y, a.z + b.z, a.w + b.w};
#pragma unroll
    for (int h = 0; h < 4; h++) {
        float v = lg[h] > 0.f ? lg[h] : NEG_SLOPE * lg[h];
        lg[h] = v;
        atomicMax(m + (long)d * 4 + h, fenc(v));
    }
    *reinterpret_cast<float4*>(att + (long)e * 4) = make_float4(lg[0], lg[1], lg[2], lg[3]);
}

// ---------------- edge pass 2: exp + segment sum (denom) ----------------
__global__ void __launch_bounds__(256) edge_exp(
    const int* __restrict__ dst, float* __restrict__ att,
    const unsigned* __restrict__ m, float* __restrict__ denom)
{
    int e = blockIdx.x * blockDim.x + threadIdx.x;
    if (e >= EDGES) return;
    int d = dst[e];
    float4 lg = *reinterpret_cast<const float4*>(att + (long)e * 4);
    uint4 mu = *reinterpret_cast<const uint4*>(m + (long)d * 4);
    float a0 = __expf(lg.x - fdec(mu.x));
    float a1 = __expf(lg.y - fdec(mu.y));
    float a2 = __expf(lg.z - fdec(mu.z));
    float a3 = __expf(lg.w - fdec(mu.w));
    atomicAdd(denom + (long)d * 4 + 0, a0);
    atomicAdd(denom + (long)d * 4 + 1, a1);
    atomicAdd(denom + (long)d * 4 + 2, a2);
    atomicAdd(denom + (long)d * 4 + 3, a3);
    *reinterpret_cast<float4*>(att + (long)e * 4) = make_float4(a0, a1, a2, a3);
}

// ---------------- edge pass 3: alpha * feat[src] scattered to agg[dst] ----------------
__global__ void __launch_bounds__(256) edge_agg(
    const int* __restrict__ src, const int* __restrict__ dst,
    const float* __restrict__ att, const float* __restrict__ denom,
    const float* __restrict__ feat, float* __restrict__ agg)
{
    int warp = (blockIdx.x * blockDim.x + threadIdx.x) >> 5;
    int lane = threadIdx.x & 31;
    if (warp >= EDGES) return;
    int s = src[warp], d = dst[warp];
    float alpha = 0.f;
    if (lane < 4)
        alpha = att[(long)warp * 4 + lane] / denom[(long)d * 4 + lane];
    int h0 = lane >> 4;
    float al0 = __shfl_sync(0xffffffffu, alpha, h0);
    float al1 = __shfl_sync(0xffffffffu, alpha, h0 + 2);
    const float4* fs = reinterpret_cast<const float4*>(feat + (long)s * FEAT);
    float4 f0 = fs[lane];
    float4 f1 = fs[lane + 32];
    float* base = agg + (long)d * FEAT;
    red4(base + lane * 4,       al0 * f0.x, al0 * f0.y, al0 * f0.z, al0 * f0.w);
    red4(base + 128 + lane * 4, al1 * f1.x, al1 * f1.y, al1 * f1.z, al1 * f1.w);
}

// ---------------- zero fill ----------------
__global__ void __launch_bounds__(256) zero_f4(float* __restrict__ p, int n4) {
    int i = blockIdx.x * blockDim.x + threadIdx.x;
    if (i < n4) reinterpret_cast<float4*>(p)[i] = make_float4(0.f, 0.f, 0.f, 0.f);
}

// ---------------- finalize: h_out = act(agg + sum_e bias[l,e]) ----------------
__global__ void __launch_bounds__(256) finalize(
    const float* __restrict__ agg, const float* __restrict__ bias_l,
    float* __restrict__ hout, int do_relu)
{
    long i = (long)blockIdx.x * blockDim.x + threadIdx.x;
    if (i >= (long)NODES * FEAT) return;
    int col = (int)(i & 255);
    float b = bias_l[col] + bias_l[256 + col] + bias_l[512 + col];
    float v = agg[i] + b;
    if (do_relu) v = fmaxf(v, 0.f);
    hout[i] = v;
}

// ---------------- launch ----------------
extern "C" void kernel_launch(void* const* d_in, const int* in_sizes, int n_in,
                              void* d_out, int out_size)
{
    const float* x      = (const float*)d_in[0];
    const float* W      = (const float*)d_in[1];
    const float* attn_l = (const float*)d_in[2];
    const float* attn_r = (const float*)d_in[3];
    const float* bias   = (const float*)d_in[4];
    const float* W_out  = (const float*)d_in[5];
    const float* b_out  = (const float*)d_in[6];
    const int*   src    = (const int*)d_in[7];
    const int*   dst    = (const int*)d_in[8];

    float *hbuf, *feat, *agg, *el, *er, *denom, *att;
    unsigned* m;
    cudaGetSymbolAddress((void**)&hbuf,  g_h);
    cudaGetSymbolAddress((void**)&feat,  g_feat);
    cudaGetSymbolAddress((void**)&agg,   g_agg);
    cudaGetSymbolAddress((void**)&el,    g_el);
    cudaGetSymbolAddress((void**)&er,    g_er);
    cudaGetSymbolAddress((void**)&m,     g_m);
    cudaGetSymbolAddress((void**)&denom, g_denom);
    cudaGetSymbolAddress((void**)&att,   g_att);

    const int GEMM_GRID_M = (NODES + 127) / 128;            // 782
    dim3 gemm_feat_grid(GEMM_GRID_M, FEAT / 128);            // y=2
    dim3 gemm_out_grid(GEMM_GRID_M, (CLASSES + 127) / 128);  // y=3

    const float* hin = x;
    for (int l = 0; l < 2; l++) {
        zero_f4<<<(NODES * FEAT / 4 + 255) / 256, 256>>>(agg, NODES * FEAT / 4);
        for (int e = 0; e < ETYPES; e++) {
            int le = l * ETYPES + e;
            const float* Wle = W + (long)le * FEAT * FEAT;
            gemm_f32x2<<<gemm_feat_grid, 256>>>(hin, Wle, feat, nullptr, NODES, FEAT);
            node_att<<<(NODES * 32 + 255) / 256, 256>>>(
                feat, attn_l + le * FEAT, attn_r + le * FEAT, el, er, m, denom);
            const int* se = src + (long)e * EDGES;
            const int* de = dst + (long)e * EDGES;
            edge_max<<<(EDGES + 255) / 256, 256>>>(se, de, el, er, att, m);
            edge_exp<<<(EDGES + 255) / 256, 256>>>(de, att, m, denom);
            edge_agg<<<(EDGES * 32 + 255) / 256, 256>>>(se, de, att, denom, feat, agg);
        }
        finalize<<<((long)NODES * FEAT + 255) / 256, 256>>>(
            agg, bias + l * ETYPES * FEAT, hbuf, (l == 0) ? 1 : 0);
        hin = hbuf;
    }
    gemm_f32x2<<<gemm_out_grid, 256>>>(hin, W_out, (float*)d_out, b_out, NODES, CLASSES);
}

// round 5
// speedup vs baseline: 1.6150x; 1.6150x over previous
#include <cuda_runtime.h>
#include <cuda_bf16.h>
#include <cstdint>

// ---------------- problem constants ----------------
constexpr int NODES  = 100000;
constexpr int EDGES  = 500000;
constexpr int ETYPES = 3;
constexpr int FEAT   = 256;   // F == H*D == K
constexpr int HEADS  = 4;
constexpr int CLASSES = 349;
constexpr int NPAD_OUT = 384;   // padded class dim (3 x 128)
constexpr float NEG_SLOPE = 0.2f;

// GEMM tiling
constexpr int STAGES = 3;
constexpr int TILE_BYTES = 128 * 80;                 // one 128x32 bf16 tile, 80B row stride
constexpr int STAGE_BYTES = 2 * TILE_BYTES;          // A + B
constexpr int GEMM_SMEM = STAGES * STAGE_BYTES;      // 61440

// ---------------- device scratch (allocation-free) ----------------
__device__ float    g_h[(size_t)NODES * FEAT];
__device__ float    g_feat[(size_t)NODES * FEAT];
__device__ float    g_agg[(size_t)NODES * FEAT];
__device__ float    g_el[NODES * HEADS];
__device__ float    g_er[NODES * HEADS];
__device__ unsigned g_m[NODES * HEADS];
__device__ float    g_denom[NODES * HEADS];
__device__ float    g_att[(size_t)EDGES * HEADS];

__device__ __nv_bfloat16 g_ahi[(size_t)NODES * FEAT];
__device__ __nv_bfloat16 g_alo[(size_t)NODES * FEAT];
__device__ __nv_bfloat16 g_wthi[6 * FEAT * FEAT];    // W^T per (layer,etype): [le][n][k]
__device__ __nv_bfloat16 g_wtlo[6 * FEAT * FEAT];
__device__ __nv_bfloat16 g_wohi[NPAD_OUT * FEAT];    // W_out^T padded: [n][k]
__device__ __nv_bfloat16 g_wolo[NPAD_OUT * FEAT];

// ---------------- small helpers ----------------
__device__ __forceinline__ unsigned fenc(float f) {
    unsigned u = __float_as_uint(f);
    return (u & 0x80000000u) ? ~u : (u | 0x80000000u);
}
__device__ __forceinline__ float fdec(unsigned u) {
    return __uint_as_float((u & 0x80000000u) ? (u ^ 0x80000000u) : ~u);
}
#define ENC_NEG_INF 0x007fffffu

__device__ __forceinline__ void red4(float* p, float a, float b, float c, float d) {
    asm volatile("red.global.add.v4.f32 [%0], {%1,%2,%3,%4};"
                 :: "l"(p), "f"(a), "f"(b), "f"(c), "f"(d) : "memory");
}

__device__ __forceinline__ uint32_t smem_u32(const void* p) {
    uint32_t a;
    asm("{ .reg .u64 t; cvta.to.shared.u64 t, %1; cvt.u32.u64 %0, t; }" : "=r"(a) : "l"(p));
    return a;
}

__device__ __forceinline__ void cp16(uint32_t dst, const void* src, uint32_t sz) {
    asm volatile("cp.async.cg.shared.global [%0], [%1], 16, %2;"
                 :: "r"(dst), "l"(src), "r"(sz) : "memory");
}
__device__ __forceinline__ void cp_commit() {
    asm volatile("cp.async.commit_group;" ::: "memory");
}
__device__ __forceinline__ void cp_wait1() {
    asm volatile("cp.async.wait_group 1;" ::: "memory");
}
__device__ __forceinline__ void cp_wait0() {
    asm volatile("cp.async.wait_group 0;" ::: "memory");
}

__device__ __forceinline__ void ldmx4(uint32_t* r, uint32_t addr) {
    asm volatile("ldmatrix.sync.aligned.m8n8.x4.shared.b16 {%0,%1,%2,%3}, [%4];"
                 : "=r"(r[0]), "=r"(r[1]), "=r"(r[2]), "=r"(r[3]) : "r"(addr));
}
__device__ __forceinline__ void mma16816(float* d, const uint32_t* a,
                                         uint32_t b0, uint32_t b1) {
    asm volatile(
        "mma.sync.aligned.m16n8k16.row.col.f32.bf16.bf16.f32 "
        "{%0,%1,%2,%3}, {%4,%5,%6,%7}, {%8,%9}, {%0,%1,%2,%3};"
        : "+f"(d[0]), "+f"(d[1]), "+f"(d[2]), "+f"(d[3])
        : "r"(a[0]), "r"(a[1]), "r"(a[2]), "r"(a[3]), "r"(b0), "r"(b1));
}

// ---------------- split / transpose prep kernels ----------------
__global__ void __launch_bounds__(256) split_f32(
    const float* __restrict__ in, __nv_bfloat16* __restrict__ hi,
    __nv_bfloat16* __restrict__ lo, int n4)
{
    int i = blockIdx.x * blockDim.x + threadIdx.x;
    if (i >= n4) return;
    float4 v = reinterpret_cast<const float4*>(in)[i];
    __nv_bfloat16 h0 = __float2bfloat16(v.x), h1 = __float2bfloat16(v.y);
    __nv_bfloat16 h2 = __float2bfloat16(v.z), h3 = __float2bfloat16(v.w);
    __nv_bfloat16 l0 = __float2bfloat16(v.x - __bfloat162float(h0));
    __nv_bfloat16 l1 = __float2bfloat16(v.y - __bfloat162float(h1));
    __nv_bfloat16 l2 = __float2bfloat16(v.z - __bfloat162float(h2));
    __nv_bfloat16 l3 = __float2bfloat16(v.w - __bfloat162float(h3));
    __nv_bfloat162* ph = reinterpret_cast<__nv_bfloat162*>(hi);
    __nv_bfloat162* pl = reinterpret_cast<__nv_bfloat162*>(lo);
    __nv_bfloat162 a; a.x = h0; a.y = h1;
    __nv_bfloat162 b; b.x = h2; b.y = h3;
    ph[i * 2] = a; ph[i * 2 + 1] = b;
    a.x = l0; a.y = l1; b.x = l2; b.y = l3;
    pl[i * 2] = a; pl[i * 2 + 1] = b;
}

__global__ void __launch_bounds__(256) prep_w(
    const float* __restrict__ W, __nv_bfloat16* __restrict__ hi,
    __nv_bfloat16* __restrict__ lo)
{
    int idx = blockIdx.x * blockDim.x + threadIdx.x;
    if (idx >= 6 * FEAT * FEAT) return;
    int le = idx >> 16;
    int r  = idx & 0xffff;
    int n  = r >> 8;
    int k  = r & 255;
    float v = W[le * FEAT * FEAT + k * FEAT + n];
    __nv_bfloat16 h = __float2bfloat16(v);
    __nv_bfloat16 l = __float2bfloat16(v - __bfloat162float(h));
    int o = le * FEAT * FEAT + n * FEAT + k;
    hi[o] = h; lo[o] = l;
}

__global__ void __launch_bounds__(256) prep_wout(
    const float* __restrict__ W_out, __nv_bfloat16* __restrict__ hi,
    __nv_bfloat16* __restrict__ lo)
{
    int idx = blockIdx.x * blockDim.x + threadIdx.x;
    if (idx >= NPAD_OUT * FEAT) return;
    int n = idx >> 8;
    int k = idx & 255;
    float v = (n < CLASSES) ? W_out[k * CLASSES + n] : 0.f;
    __nv_bfloat16 h = __float2bfloat16(v);
    __nv_bfloat16 l = __float2bfloat16(v - __bfloat162float(h));
    hi[n * FEAT + k] = h; lo[n * FEAT + k] = l;
}

// ---------------- tensor-core GEMM (mma.sync bf16, 3-term compensated) ----------
// C[M,Ncols] = Ahi@Bhi^T + Ahi@Blo^T + Alo@Bhi^T (+bias)
// A*: [M,256] bf16 row-major. B*: [Npad,256] bf16 row-major (i.e. W^T).
// CTA: 128x128 tile, 8 warps (2M x 4N), warp tile 64x32. BK=32, 3-stage cp.async.
__global__ void __launch_bounds__(256, 2) gemm_mma(
    const __nv_bfloat16* __restrict__ Ahi, const __nv_bfloat16* __restrict__ Alo,
    const __nv_bfloat16* __restrict__ Bhi, const __nv_bfloat16* __restrict__ Blo,
    float* __restrict__ C, const float* __restrict__ bias, int M, int Ncols)
{
    extern __shared__ char smem[];
    const uint32_t sbase = smem_u32(smem);
    const int tid  = threadIdx.x;
    const int lane = tid & 31;
    const int warp = tid >> 5;
    const int wm = (warp & 1) * 64;
    const int wn = (warp >> 1) * 32;
    const long bm = (long)blockIdx.x * 128;
    const int bn  = blockIdx.y * 128;

    float acc[4][4][4];
#pragma unroll
    for (int i = 0; i < 4; i++)
#pragma unroll
        for (int j = 0; j < 4; j++)
#pragma unroll
            for (int q = 0; q < 4; q++) acc[i][j][q] = 0.f;

    const int NITER = 24;   // 3 passes x 8 k-chunks of 32

    // --- async stage loader ---
    auto issue = [&](int it) {
        const int p  = it >> 3;
        const int kc = it & 7;
        const __nv_bfloat16* Ag = (p < 2) ? Ahi : Alo;
        const __nv_bfloat16* Bg = (p == 1) ? Blo : Bhi;
        const uint32_t sa = sbase + (it % STAGES) * STAGE_BYTES;
        const uint32_t sb = sa + TILE_BYTES;
#pragma unroll
        for (int q = 0; q < 2; q++) {
            int idx = tid * 2 + q;          // 0..511
            int row = idx >> 2;
            int ch  = idx & 3;
            long ar = bm + row;
            long arc = ar < (M - 1) ? ar : (M - 1);
            const void* srcA = Ag + arc * 256 + kc * 32 + ch * 8;
            cp16(sa + row * 80 + ch * 16, srcA, (ar < M) ? 16u : 0u);
            const void* srcB = Bg + (long)(bn + row) * 256 + kc * 32 + ch * 8;
            cp16(sb + row * 80 + ch * 16, srcB, 16u);
        }
        cp_commit();
    };

    issue(0);
    issue(1);

    for (int it = 0; it < NITER; it++) {
        cp_wait1();
        __syncthreads();
        if (it + 2 < NITER) issue(it + 2);

        const uint32_t sa = sbase + (it % STAGES) * STAGE_BYTES;
        const uint32_t sb = sa + TILE_BYTES;
#pragma unroll
        for (int ks = 0; ks < 2; ks++) {
            uint32_t a[4][4];
#pragma unroll
            for (int mt = 0; mt < 4; mt++)
                ldmx4(a[mt], sa + (wm + mt * 16 + (lane & 15)) * 80
                              + ks * 32 + (lane >> 4) * 16);
            uint32_t b[2][4];
#pragma unroll
            for (int jb = 0; jb < 2; jb++)
                ldmx4(b[jb], sb + (wn + jb * 16 + ((lane >> 4) << 3) + (lane & 7)) * 80
                              + ks * 32 + ((lane >> 3) & 1) * 16);
#pragma unroll
            for (int mt = 0; mt < 4; mt++)
#pragma unroll
                for (int nt = 0; nt < 4; nt++)
                    mma16816(acc[mt][nt], a[mt],
                             b[nt >> 1][(nt & 1) * 2], b[nt >> 1][(nt & 1) * 2 + 1]);
        }
        __syncthreads();
    }
    cp_wait0();

    // --- epilogue: registers -> global ---
    const bool even = ((Ncols & 1) == 0);
#pragma unroll
    for (int mt = 0; mt < 4; mt++) {
#pragma unroll
        for (int nt = 0; nt < 4; nt++) {
            int c0 = bn + wn + nt * 8 + (lane & 3) * 2;
            float b0 = 0.f, b1 = 0.f;
            if (bias) {
                if (c0 < Ncols)     b0 = bias[c0];
                if (c0 + 1 < Ncols) b1 = bias[c0 + 1];
            }
#pragma unroll
            for (int half = 0; half < 2; half++) {
                long row = bm + wm + mt * 16 + (lane >> 2) + half * 8;
                if (row >= M) continue;
                float v0 = acc[mt][nt][half * 2 + 0] + b0;
                float v1 = acc[mt][nt][half * 2 + 1] + b1;
                float* crow = C + row * Ncols;
                if (even && (c0 + 1) < Ncols) {
                    *reinterpret_cast<float2*>(crow + c0) = make_float2(v0, v1);
                } else {
                    if (c0 < Ncols)     crow[c0] = v0;
                    if (c0 + 1 < Ncols) crow[c0 + 1] = v1;
                }
            }
        }
    }
}

// ---------------- per-node attention dots + reset m/denom ----------------
__global__ void __launch_bounds__(256) node_att(
    const float* __restrict__ feat,
    const float* __restrict__ al, const float* __restrict__ ar,
    float* __restrict__ el, float* __restrict__ er,
    unsigned* __restrict__ m, float* __restrict__ denom)
{
    int warp = (blockIdx.x * blockDim.x + threadIdx.x) >> 5;
    int lane = threadIdx.x & 31;
    if (warp >= NODES) return;
    const float4* frow = reinterpret_cast<const float4*>(feat + (long)warp * FEAT);
    const float4* alv  = reinterpret_cast<const float4*>(al);
    const float4* arv  = reinterpret_cast<const float4*>(ar);
    float sl = 0.f, sr = 0.f;
#pragma unroll
    for (int q = 0; q < 2; q++) {
        int idx = lane * 2 + q;
        float4 f = frow[idx], a = alv[idx], b = arv[idx];
        sl += f.x * a.x + f.y * a.y + f.z * a.z + f.w * a.w;
        sr += f.x * b.x + f.y * b.y + f.z * b.z + f.w * b.w;
    }
#pragma unroll
    for (int off = 4; off >= 1; off >>= 1) {
        sl += __shfl_xor_sync(0xffffffffu, sl, off);
        sr += __shfl_xor_sync(0xffffffffu, sr, off);
    }
    if ((lane & 7) == 0) {
        int h = lane >> 3;
        el[warp * HEADS + h] = sl;
        er[warp * HEADS + h] = sr;
    }
    if (lane < HEADS) {
        m[warp * HEADS + lane] = ENC_NEG_INF;
        denom[warp * HEADS + lane] = 0.f;
    }
}

// ---------------- edge passes ----------------
__global__ void __launch_bounds__(256) edge_max(
    const int* __restrict__ src, const int* __restrict__ dst,
    const float* __restrict__ el, const float* __restrict__ er,
    float* __restrict__ att, unsigned* __restrict__ m)
{
    int e = blockIdx.x * blockDim.x + threadIdx.x;
    if (e >= EDGES) return;
    int s = src[e], d = dst[e];
    float4 a = *reinterpret_cast<const float4*>(el + (long)s * 4);
    float4 b = *reinterpret_cast<const float4*>(er + (long)d * 4);
    float lg[4] = {a.x + b.x, a.y + b.y, a.z + b.z, a.w + b.w};
#pragma unroll
    for (int h = 0; h < 4; h++) {
        float v = lg[h] > 0.f ? lg[h] : NEG_SLOPE * lg[h];
        lg[h] = v;
        atomicMax(m + (long)d * 4 + h, fenc(v));
    }
    *reinterpret_cast<float4*>(att + (long)e * 4) = make_float4(lg[0], lg[1], lg[2], lg[3]);
}

__global__ void __launch_bounds__(256) edge_exp(
    const int* __restrict__ dst, float* __restrict__ att,
    const unsigned* __restrict__ m, float* __restrict__ denom)
{
    int e = blockIdx.x * blockDim.x + threadIdx.x;
    if (e >= EDGES) return;
    int d = dst[e];
    float4 lg = *reinterpret_cast<const float4*>(att + (long)e * 4);
    uint4 mu = *reinterpret_cast<const uint4*>(m + (long)d * 4);
    float a0 = __expf(lg.x - fdec(mu.x));
    float a1 = __expf(lg.y - fdec(mu.y));
    float a2 = __expf(lg.z - fdec(mu.z));
    float a3 = __expf(lg.w - fdec(mu.w));
    atomicAdd(denom + (long)d * 4 + 0, a0);
    atomicAdd(denom + (long)d * 4 + 1, a1);
    atomicAdd(denom + (long)d * 4 + 2, a2);
    atomicAdd(denom + (long)d * 4 + 3, a3);
    *reinterpret_cast<float4*>(att + (long)e * 4) = make_float4(a0, a1, a2, a3);
}

__global__ void __launch_bounds__(256) edge_agg(
    const int* __restrict__ src, const int* __restrict__ dst,
    const float* __restrict__ att, const float* __restrict__ denom,
    const float* __restrict__ feat, float* __restrict__ agg)
{
    int warp = (blockIdx.x * blockDim.x + threadIdx.x) >> 5;
    int lane = threadIdx.x & 31;
    if (warp >= EDGES) return;
    int s = src[warp], d = dst[warp];
    float alpha = 0.f;
    if (lane < 4)
        alpha = att[(long)warp * 4 + lane] / denom[(long)d * 4 + lane];
    int h0 = lane >> 4;
    float al0 = __shfl_sync(0xffffffffu, alpha, h0);
    float al1 = __shfl_sync(0xffffffffu, alpha, h0 + 2);
    const float4* fs = reinterpret_cast<const float4*>(feat + (long)s * FEAT);
    float4 f0 = fs[lane];
    float4 f1 = fs[lane + 32];
    float* base = agg + (long)d * FEAT;
    red4(base + lane * 4,       al0 * f0.x, al0 * f0.y, al0 * f0.z, al0 * f0.w);
    red4(base + 128 + lane * 4, al1 * f1.x, al1 * f1.y, al1 * f1.z, al1 * f1.w);
}

// ---------------- misc ----------------
__global__ void __launch_bounds__(256) zero_f4(float* __restrict__ p, int n4) {
    int i = blockIdx.x * blockDim.x + threadIdx.x;
    if (i < n4) reinterpret_cast<float4*>(p)[i] = make_float4(0.f, 0.f, 0.f, 0.f);
}

__global__ void __launch_bounds__(256) finalize(
    const float* __restrict__ agg, const float* __restrict__ bias_l,
    float* __restrict__ hout, int do_relu)
{
    long i = (long)blockIdx.x * blockDim.x + threadIdx.x;
    if (i >= (long)NODES * FEAT) return;
    int col = (int)(i & 255);
    float b = bias_l[col] + bias_l[256 + col] + bias_l[512 + col];
    float v = agg[i] + b;
    if (do_relu) v = fmaxf(v, 0.f);
    hout[i] = v;
}

// ---------------- launch ----------------
extern "C" void kernel_launch(void* const* d_in, const int* in_sizes, int n_in,
                              void* d_out, int out_size)
{
    const float* x      = (const float*)d_in[0];
    const float* W      = (const float*)d_in[1];
    const float* attn_l = (const float*)d_in[2];
    const float* attn_r = (const float*)d_in[3];
    const float* bias   = (const float*)d_in[4];
    const float* W_out  = (const float*)d_in[5];
    const float* b_out  = (const float*)d_in[6];
    const int*   src    = (const int*)d_in[7];
    const int*   dst    = (const int*)d_in[8];

    float *hbuf, *feat, *agg, *el, *er, *denom, *att;
    unsigned* m;
    __nv_bfloat16 *ahi, *alo, *wthi, *wtlo, *wohi, *wolo;
    cudaGetSymbolAddress((void**)&hbuf,  g_h);
    cudaGetSymbolAddress((void**)&feat,  g_feat);
    cudaGetSymbolAddress((void**)&agg,   g_agg);
    cudaGetSymbolAddress((void**)&el,    g_el);
    cudaGetSymbolAddress((void**)&er,    g_er);
    cudaGetSymbolAddress((void**)&m,     g_m);
    cudaGetSymbolAddress((void**)&denom, g_denom);
    cudaGetSymbolAddress((void**)&att,   g_att);
    cudaGetSymbolAddress((void**)&ahi,   g_ahi);
    cudaGetSymbolAddress((void**)&alo,   g_alo);
    cudaGetSymbolAddress((void**)&wthi,  g_wthi);
    cudaGetSymbolAddress((void**)&wtlo,  g_wtlo);
    cudaGetSymbolAddress((void**)&wohi,  g_wohi);
    cudaGetSymbolAddress((void**)&wolo,  g_wolo);

    cudaFuncSetAttribute(gemm_mma, cudaFuncAttributeMaxDynamicSharedMemorySize, GEMM_SMEM);

    // prep: weight transpose+split, initial A split
    prep_w<<<(6 * FEAT * FEAT + 255) / 256, 256>>>(W, wthi, wtlo);
    prep_wout<<<(NPAD_OUT * FEAT + 255) / 256, 256>>>(W_out, wohi, wolo);
    split_f32<<<(NODES * FEAT / 4 + 255) / 256, 256>>>(x, ahi, alo, NODES * FEAT / 4);

    const int GRID_M = (NODES + 127) / 128;   // 782
    dim3 feat_grid(GRID_M, 2);                // N=256
    dim3 out_grid(GRID_M, 3);                 // Npad=384

    for (int l = 0; l < 2; l++) {
        zero_f4<<<(NODES * FEAT / 4 + 255) / 256, 256>>>(agg, NODES * FEAT / 4);
        for (int e = 0; e < ETYPES; e++) {
            int le = l * ETYPES + e;
            gemm_mma<<<feat_grid, 256, GEMM_SMEM>>>(
                ahi, alo, wthi + (long)le * FEAT * FEAT, wtlo + (long)le * FEAT * FEAT,
                feat, nullptr, NODES, FEAT);
            node_att<<<(NODES * 32 + 255) / 256, 256>>>(
                feat, attn_l + le * FEAT, attn_r + le * FEAT, el, er, m, denom);
            const int* se = src + (long)e * EDGES;
            const int* de = dst + (long)e * EDGES;
            edge_max<<<(EDGES + 255) / 256, 256>>>(se, de, el, er, att, m);
            edge_exp<<<(EDGES + 255) / 256, 256>>>(de, att, m, denom);
            edge_agg<<<(EDGES * 32 + 255) / 256, 256>>>(se, de, att, denom, feat, agg);
        }
        finalize<<<((long)NODES * FEAT + 255) / 256, 256>>>(
            agg, bias + l * ETYPES * FEAT, hbuf, (l == 0) ? 1 : 0);
        split_f32<<<(NODES * FEAT / 4 + 255) / 256, 256>>>(hbuf, ahi, alo, NODES * FEAT / 4);
    }
    gemm_mma<<<out_grid, 256, GEMM_SMEM>>>(
        ahi, alo, wohi, wolo, (float*)d_out, b_out, NODES, CLASSES);
}

// round 6
// speedup vs baseline: 2.0776x; 1.2865x over previous
#include <cuda_runtime.h>
#include <cuda_fp16.h>
#include <cstdint>

// ---------------- problem constants ----------------
constexpr int NODES  = 100000;
constexpr int EDGES  = 500000;
constexpr int ETYPES = 3;
constexpr int FEAT   = 256;   // F == H*D == K
constexpr int HEADS  = 4;
constexpr int CLASSES = 349;
constexpr int NPAD_OUT = 384;   // padded class dim (3 x 128)
constexpr float NEG_SLOPE = 0.2f;

// GEMM tiling
constexpr int STAGES = 3;
constexpr int TILE_BYTES = 128 * 80;                 // one 128x32 fp16 tile, 80B row stride
constexpr int STAGE_BYTES = 2 * TILE_BYTES;          // A + B
constexpr int GEMM_SMEM = STAGES * STAGE_BYTES;      // 61440

// ---------------- device scratch (allocation-free) ----------------
__device__ float  g_feat[(size_t)NODES * FEAT];
__device__ float  g_agg[(size_t)NODES * FEAT];
__device__ float  g_el[NODES * HEADS];
__device__ float  g_er[NODES * HEADS];
__device__ float  g_denom[NODES * HEADS];
__device__ float  g_att[(size_t)EDGES * HEADS];
__device__ float  g_bsum[FEAT];

__device__ __half g_ahi[(size_t)NODES * FEAT];
__device__ __half g_alo[(size_t)NODES * FEAT];
__device__ __half g_whi[6 * FEAT * FEAT];    // W^T per (layer,etype): [le][n][k]
__device__ __half g_wohi[NPAD_OUT * FEAT];   // W_out^T padded: [n][k]

// ---------------- small helpers ----------------
__device__ __forceinline__ void red4(float* p, float a, float b, float c, float d) {
    asm volatile("red.global.add.v4.f32 [%0], {%1,%2,%3,%4};"
                 :: "l"(p), "f"(a), "f"(b), "f"(c), "f"(d) : "memory");
}

__device__ __forceinline__ uint32_t smem_u32(const void* p) {
    uint32_t a;
    asm("{ .reg .u64 t; cvta.to.shared.u64 t, %1; cvt.u32.u64 %0, t; }" : "=r"(a) : "l"(p));
    return a;
}

__device__ __forceinline__ void cp16(uint32_t dst, const void* src, uint32_t sz) {
    asm volatile("cp.async.cg.shared.global [%0], [%1], 16, %2;"
                 :: "r"(dst), "l"(src), "r"(sz) : "memory");
}
__device__ __forceinline__ void cp_commit() {
    asm volatile("cp.async.commit_group;" ::: "memory");
}
__device__ __forceinline__ void cp_wait1() {
    asm volatile("cp.async.wait_group 1;" ::: "memory");
}
__device__ __forceinline__ void cp_wait0() {
    asm volatile("cp.async.wait_group 0;" ::: "memory");
}

__device__ __forceinline__ void ldmx4(uint32_t* r, uint32_t addr) {
    asm volatile("ldmatrix.sync.aligned.m8n8.x4.shared.b16 {%0,%1,%2,%3}, [%4];"
                 : "=r"(r[0]), "=r"(r[1]), "=r"(r[2]), "=r"(r[3]) : "r"(addr));
}
__device__ __forceinline__ void mma16816(float* d, const uint32_t* a,
                                         uint32_t b0, uint32_t b1) {
    asm volatile(
        "mma.sync.aligned.m16n8k16.row.col.f32.f16.f16.f32 "
        "{%0,%1,%2,%3}, {%4,%5,%6,%7}, {%8,%9}, {%0,%1,%2,%3};"
        : "+f"(d[0]), "+f"(d[1]), "+f"(d[2]), "+f"(d[3])
        : "r"(a[0]), "r"(a[1]), "r"(a[2]), "r"(a[3]), "r"(b0), "r"(b1));
}

// ---------------- prep kernels ----------------
// split fp32 -> fp16 hi + fp16 lo (residual)
__global__ void __launch_bounds__(256) split_f32(
    const float* __restrict__ in, __half* __restrict__ hi,
    __half* __restrict__ lo, int n4)
{
    int i = blockIdx.x * blockDim.x + threadIdx.x;
    if (i >= n4) return;
    float4 v = reinterpret_cast<const float4*>(in)[i];
    __half h0 = __float2half_rn(v.x), h1 = __float2half_rn(v.y);
    __half h2 = __float2half_rn(v.z), h3 = __float2half_rn(v.w);
    __half l0 = __float2half_rn(v.x - __half2float(h0));
    __half l1 = __float2half_rn(v.y - __half2float(h1));
    __half l2 = __float2half_rn(v.z - __half2float(h2));
    __half l3 = __float2half_rn(v.w - __half2float(h3));
    __half2* ph = reinterpret_cast<__half2*>(hi);
    __half2* pl = reinterpret_cast<__half2*>(lo);
    ph[i * 2]     = __halves2half2(h0, h1);
    ph[i * 2 + 1] = __halves2half2(h2, h3);
    pl[i * 2]     = __halves2half2(l0, l1);
    pl[i * 2 + 1] = __halves2half2(l2, l3);
}

__global__ void __launch_bounds__(256) prep_w(
    const float* __restrict__ W, __half* __restrict__ hi)
{
    int idx = blockIdx.x * blockDim.x + threadIdx.x;
    if (idx >= 6 * FEAT * FEAT) return;
    int le = idx >> 16;
    int r  = idx & 0xffff;
    int n  = r >> 8;
    int k  = r & 255;
    float v = W[le * FEAT * FEAT + k * FEAT + n];
    hi[le * FEAT * FEAT + n * FEAT + k] = __float2half_rn(v);
}

__global__ void __launch_bounds__(256) prep_wout(
    const float* __restrict__ W_out, __half* __restrict__ hi)
{
    int idx = blockIdx.x * blockDim.x + threadIdx.x;
    if (idx >= NPAD_OUT * FEAT) return;
    int n = idx >> 8;
    int k = idx & 255;
    float v = (n < CLASSES) ? W_out[k * CLASSES + n] : 0.f;
    hi[n * FEAT + k] = __float2half_rn(v);
}

__global__ void bias_sum(const float* __restrict__ bias_l, float* __restrict__ bsum) {
    int c = threadIdx.x;
    bsum[c] = bias_l[c] + bias_l[256 + c] + bias_l[512 + c];
}

// ---------------- tensor-core GEMM (mma.sync fp16, 2-pass A-compensated) ------
// C[M,Ncols] = Ahi@B^T + Alo@B^T (+bias), fp32 accum.
// A*: [M,256] fp16 row-major. B: [Npad,256] fp16 row-major (i.e. W^T).
// CTA: 128x128 tile, 8 warps (2M x 4N), warp tile 64x32. BK=32, 3-stage cp.async.
__global__ void __launch_bounds__(256, 2) gemm_mma(
    const __half* __restrict__ Ahi, const __half* __restrict__ Alo,
    const __half* __restrict__ B,
    float* __restrict__ C, const float* __restrict__ bias, int M, int Ncols)
{
    extern __shared__ char smem[];
    const uint32_t sbase = smem_u32(smem);
    const int tid  = threadIdx.x;
    const int lane = tid & 31;
    const int warp = tid >> 5;
    const int wm = (warp & 1) * 64;
    const int wn = (warp >> 1) * 32;
    const long bm = (long)blockIdx.x * 128;
    const int bn  = blockIdx.y * 128;

    float acc[4][4][4];
#pragma unroll
    for (int i = 0; i < 4; i++)
#pragma unroll
        for (int j = 0; j < 4; j++)
#pragma unroll
            for (int q = 0; q < 4; q++) acc[i][j][q] = 0.f;

    const int NITER = 16;   // 2 passes x 8 k-chunks of 32

    auto issue = [&](int it) {
        const int p  = it >> 3;
        const int kc = it & 7;
        const __half* Ag = (p == 0) ? Ahi : Alo;
        const uint32_t sa = sbase + (it % STAGES) * STAGE_BYTES;
        const uint32_t sb = sa + TILE_BYTES;
#pragma unroll
        for (int q = 0; q < 2; q++) {
            int idx = tid * 2 + q;          // 0..511
            int row = idx >> 2;
            int ch  = idx & 3;
            long ar = bm + row;
            long arc = ar < (M - 1) ? ar : (M - 1);
            const void* srcA = Ag + arc * 256 + kc * 32 + ch * 8;
            cp16(sa + row * 80 + ch * 16, srcA, (ar < M) ? 16u : 0u);
            const void* srcB = B + (long)(bn + row) * 256 + kc * 32 + ch * 8;
            cp16(sb + row * 80 + ch * 16, srcB, 16u);
        }
        cp_commit();
    };

    issue(0);
    issue(1);

    for (int it = 0; it < NITER; it++) {
        cp_wait1();
        __syncthreads();
        if (it + 2 < NITER) issue(it + 2);

        const uint32_t sa = sbase + (it % STAGES) * STAGE_BYTES;
        const uint32_t sb = sa + TILE_BYTES;
#pragma unroll
        for (int ks = 0; ks < 2; ks++) {
            uint32_t a[4][4];
#pragma unroll
            for (int mt = 0; mt < 4; mt++)
                ldmx4(a[mt], sa + (wm + mt * 16 + (lane & 15)) * 80
                              + ks * 32 + (lane >> 4) * 16);
            uint32_t b[2][4];
#pragma unroll
            for (int jb = 0; jb < 2; jb++)
                ldmx4(b[jb], sb + (wn + jb * 16 + ((lane >> 4) << 3) + (lane & 7)) * 80
                              + ks * 32 + ((lane >> 3) & 1) * 16);
#pragma unroll
            for (int mt = 0; mt < 4; mt++)
#pragma unroll
                for (int nt = 0; nt < 4; nt++)
                    mma16816(acc[mt][nt], a[mt],
                             b[nt >> 1][(nt & 1) * 2], b[nt >> 1][(nt & 1) * 2 + 1]);
        }
        __syncthreads();
    }
    cp_wait0();

    // --- epilogue ---
    const bool even = ((Ncols & 1) == 0);
#pragma unroll
    for (int mt = 0; mt < 4; mt++) {
#pragma unroll
        for (int nt = 0; nt < 4; nt++) {
            int c0 = bn + wn + nt * 8 + (lane & 3) * 2;
            float b0 = 0.f, b1 = 0.f;
            if (bias) {
                if (c0 < Ncols)     b0 = bias[c0];
                if (c0 + 1 < Ncols) b1 = bias[c0 + 1];
            }
#pragma unroll
            for (int half = 0; half < 2; half++) {
                long row = bm + wm + mt * 16 + (lane >> 2) + half * 8;
                if (row >= M) continue;
                float v0 = acc[mt][nt][half * 2 + 0] + b0;
                float v1 = acc[mt][nt][half * 2 + 1] + b1;
                float* crow = C + row * Ncols;
                if (even && (c0 + 1) < Ncols) {
                    *reinterpret_cast<float2*>(crow + c0) = make_float2(v0, v1);
                } else {
                    if (c0 < Ncols)     crow[c0] = v0;
                    if (c0 + 1 < Ncols) crow[c0 + 1] = v1;
                }
            }
        }
    }
}

// ---------------- per-node attention dots + reset denom ----------------
__global__ void __launch_bounds__(256) node_att(
    const float* __restrict__ feat,
    const float* __restrict__ al, const float* __restrict__ ar,
    float* __restrict__ el, float* __restrict__ er, float* __restrict__ denom)
{
    int warp = (blockIdx.x * blockDim.x + threadIdx.x) >> 5;
    int lane = threadIdx.x & 31;
    if (warp >= NODES) return;
    const float4* frow = reinterpret_cast<const float4*>(feat + (long)warp * FEAT);
    const float4* alv  = reinterpret_cast<const float4*>(al);
    const float4* arv  = reinterpret_cast<const float4*>(ar);
    float sl = 0.f, sr = 0.f;
#pragma unroll
    for (int q = 0; q < 2; q++) {
        int idx = lane * 2 + q;
        float4 f = frow[idx], a = alv[idx], b = arv[idx];
        sl += f.x * a.x + f.y * a.y + f.z * a.z + f.w * a.w;
        sr += f.x * b.x + f.y * b.y + f.z * b.z + f.w * b.w;
    }
#pragma unroll
    for (int off = 4; off >= 1; off >>= 1) {
        sl += __shfl_xor_sync(0xffffffffu, sl, off);
        sr += __shfl_xor_sync(0xffffffffu, sr, off);
    }
    if ((lane & 7) == 0) {
        int h = lane >> 3;
        el[warp * HEADS + h] = sl;
        er[warp * HEADS + h] = sr;
    }
    if (lane < HEADS) denom[warp * HEADS + lane] = 0.f;
}

// ---------------- edge pass 1: logits -> exp -> denom (max-free softmax) ------
__global__ void __launch_bounds__(256) edge_exp(
    const int* __restrict__ src, const int* __restrict__ dst,
    const float* __restrict__ el, const float* __restrict__ er,
    float* __restrict__ att, float* __restrict__ denom)
{
    int e = blockIdx.x * blockDim.x + threadIdx.x;
    if (e >= EDGES) return;
    int s = src[e], d = dst[e];
    float4 a = *reinterpret_cast<const float4*>(el + (long)s * 4);
    float4 b = *reinterpret_cast<const float4*>(er + (long)d * 4);
    float lg[4] = {a.x + b.x, a.y + b.y, a.z + b.z, a.w + b.w};
    float ex[4];
#pragma unroll
    for (int h = 0; h < 4; h++) {
        float v = lg[h] > 0.f ? lg[h] : NEG_SLOPE * lg[h];
        ex[h] = __expf(v);
    }
    atomicAdd(denom + (long)d * 4 + 0, ex[0]);
    atomicAdd(denom + (long)d * 4 + 1, ex[1]);
    atomicAdd(denom + (long)d * 4 + 2, ex[2]);
    atomicAdd(denom + (long)d * 4 + 3, ex[3]);
    *reinterpret_cast<float4*>(att + (long)e * 4) = make_float4(ex[0], ex[1], ex[2], ex[3]);
}

// ---------------- edge pass 2: alpha * feat[src] scattered to agg[dst] --------
__global__ void __launch_bounds__(256) edge_agg(
    const int* __restrict__ src, const int* __restrict__ dst,
    const float* __restrict__ att, const float* __restrict__ denom,
    const float* __restrict__ feat, float* __restrict__ agg)
{
    int warp = (blockIdx.x * blockDim.x + threadIdx.x) >> 5;
    int lane = threadIdx.x & 31;
    if (warp >= EDGES) return;
    int s = src[warp], d = dst[warp];
    float alpha = 0.f;
    if (lane < 4)
        alpha = att[(long)warp * 4 + lane] / denom[(long)d * 4 + lane];
    int h0 = lane >> 4;
    float al0 = __shfl_sync(0xffffffffu, alpha, h0);
    float al1 = __shfl_sync(0xffffffffu, alpha, h0 + 2);
    const float4* fs = reinterpret_cast<const float4*>(feat + (long)s * FEAT);
    float4 f0 = fs[lane];
    float4 f1 = fs[lane + 32];
    float* base = agg + (long)d * FEAT;
    red4(base + lane * 4,       al0 * f0.x, al0 * f0.y, al0 * f0.z, al0 * f0.w);
    red4(base + 128 + lane * 4, al1 * f1.x, al1 * f1.y, al1 * f1.z, al1 * f1.w);
}

// ---------------- misc ----------------
__global__ void __launch_bounds__(256) zero_f4(float* __restrict__ p, int n4) {
    int i = blockIdx.x * blockDim.x + threadIdx.x;
    if (i < n4) reinterpret_cast<float4*>(p)[i] = make_float4(0.f, 0.f, 0.f, 0.f);
}

// finalize + split fused: h = act(agg + bsum) -> (ahi, alo) fp16 splits
__global__ void __launch_bounds__(256) finalize_split(
    const float* __restrict__ agg, const float* __restrict__ bsum,
    __half* __restrict__ hi, __half* __restrict__ lo, int do_relu)
{
    int i = blockIdx.x * blockDim.x + threadIdx.x;
    if (i >= NODES * FEAT / 4) return;
    float4 v = reinterpret_cast<const float4*>(agg)[i];
    int c = (i & 63) * 4;
    float4 b = *reinterpret_cast<const float4*>(bsum + c);
    v.x += b.x; v.y += b.y; v.z += b.z; v.w += b.w;
    if (do_relu) {
        v.x = fmaxf(v.x, 0.f); v.y = fmaxf(v.y, 0.f);
        v.z = fmaxf(v.z, 0.f); v.w = fmaxf(v.w, 0.f);
    }
    __half h0 = __float2half_rn(v.x), h1 = __float2half_rn(v.y);
    __half h2 = __float2half_rn(v.z), h3 = __float2half_rn(v.w);
    __half l0 = __float2half_rn(v.x - __half2float(h0));
    __half l1 = __float2half_rn(v.y - __half2float(h1));
    __half l2 = __float2half_rn(v.z - __half2float(h2));
    __half l3 = __float2half_rn(v.w - __half2float(h3));
    __half2* ph = reinterpret_cast<__half2*>(hi);
    __half2* pl = reinterpret_cast<__half2*>(lo);
    ph[i * 2]     = __halves2half2(h0, h1);
    ph[i * 2 + 1] = __halves2half2(h2, h3);
    pl[i * 2]     = __halves2half2(l0, l1);
    pl[i * 2 + 1] = __halves2half2(l2, l3);
}

// ---------------- launch ----------------
extern "C" void kernel_launch(void* const* d_in, const int* in_sizes, int n_in,
                              void* d_out, int out_size)
{
    const float* x      = (const float*)d_in[0];
    const float* W      = (const float*)d_in[1];
    const float* attn_l = (const float*)d_in[2];
    const float* attn_r = (const float*)d_in[3];
    const float* bias   = (const float*)d_in[4];
    const float* W_out  = (const float*)d_in[5];
    const float* b_out  = (const float*)d_in[6];
    const int*   src    = (const int*)d_in[7];
    const int*   dst    = (const int*)d_in[8];

    float *feat, *agg, *el, *er, *denom, *att, *bsum;
    __half *ahi, *alo, *whi, *wohi;
    cudaGetSymbolAddress((void**)&feat,  g_feat);
    cudaGetSymbolAddress((void**)&agg,   g_agg);
    cudaGetSymbolAddress((void**)&el,    g_el);
    cudaGetSymbolAddress((void**)&er,    g_er);
    cudaGetSymbolAddress((void**)&denom, g_denom);
    cudaGetSymbolAddress((void**)&att,   g_att);
    cudaGetSymbolAddress((void**)&bsum,  g_bsum);
    cudaGetSymbolAddress((void**)&ahi,   g_ahi);
    cudaGetSymbolAddress((void**)&alo,   g_alo);
    cudaGetSymbolAddress((void**)&whi,   g_whi);
    cudaGetSymbolAddress((void**)&wohi,  g_wohi);

    cudaFuncSetAttribute(gemm_mma, cudaFuncAttributeMaxDynamicSharedMemorySize, GEMM_SMEM);

    prep_w<<<(6 * FEAT * FEAT + 255) / 256, 256>>>(W, whi);
    prep_wout<<<(NPAD_OUT * FEAT + 255) / 256, 256>>>(W_out, wohi);
    split_f32<<<(NODES * FEAT / 4 + 255) / 256, 256>>>(x, ahi, alo, NODES * FEAT / 4);

    const int GRID_M = (NODES + 127) / 128;   // 782
    dim3 feat_grid(GRID_M, 2);                // N=256
    dim3 out_grid(GRID_M, 3);                 // Npad=384

    for (int l = 0; l < 2; l++) {
        zero_f4<<<(NODES * FEAT / 4 + 255) / 256, 256>>>(agg, NODES * FEAT / 4);
        for (int e = 0; e < ETYPES; e++) {
            int le = l * ETYPES + e;
            gemm_mma<<<feat_grid, 256, GEMM_SMEM>>>(
                ahi, alo, whi + (long)le * FEAT * FEAT, feat, nullptr, NODES, FEAT);
            node_att<<<(NODES * 32 + 255) / 256, 256>>>(
                feat, attn_l + le * FEAT, attn_r + le * FEAT, el, er, denom);
            const int* se = src + (long)e * EDGES;
            const int* de = dst + (long)e * EDGES;
            edge_exp<<<(EDGES + 255) / 256, 256>>>(se, de, el, er, att, denom);
            edge_agg<<<(EDGES * 32 + 255) / 256, 256>>>(se, de, att, denom, feat, agg);
        }
        bias_sum<<<1, 256>>>(bias + l * ETYPES * FEAT, bsum);
        finalize_split<<<(NODES * FEAT / 4 + 255) / 256, 256>>>(
            agg, bsum, ahi, alo, (l == 0) ? 1 : 0);
    }
    gemm_mma<<<out_grid, 256, GEMM_SMEM>>>(
        ahi, alo, wohi, (float*)d_out, b_out, NODES, CLASSES);
}